// round 1
// baseline (speedup 1.0000x reference)
#include <cuda_runtime.h>
#include <math.h>
#include <stdint.h>

// ---------------- problem constants ----------------
#define H_IN 2048
#define W_IN 2048
#define P1   1023            // after conv1(2046) + maxpool2
#define C2   1021            // after conv2
#define C3   1019            // after conv3
#define NPIX (C3*C3)         // 1038361
#define NBINS 8192
#define CANDMAX 4096
#define KTOP 512

// ---------------- scratch (device globals; no allocation allowed) ----------
__device__ float g_pool1[10 * P1 * P1];     // ~41.9 MB
__device__ float g_h2[16 * C2 * C2];        // ~66.7 MB
__device__ float g_prob[NPIX];              // ~4.2 MB
__device__ float4 g_reg[NPIX];              // ~16.6 MB
__device__ int   g_hist[NBINS];
__device__ int   g_cut;
__device__ int   g_cnt;
__device__ unsigned long long g_cand[CANDMAX];
__device__ float g_box5[KTOP * 5];

// ---------------- weights in constant memory ----------------
__constant__ float cw1[270], cb1[10], cp1[10];
__constant__ float cw2[1440], cb2[16], cp2[16];
__constant__ float cw3[4608], cb3[32], cp3[32];
__constant__ float cwa[64], cba[2], cwb[128], cbb[4];

// ============ K1: conv1(3->10,3x3) + PReLU + maxpool2 fused ============
__global__ void k1(const float* __restrict__ x) {
    int j = blockIdx.x * 16 + threadIdx.x;
    int i = blockIdx.y * 16 + threadIdx.y;
    if (i >= P1 || j >= P1) return;

    float p[3][4][4];
#pragma unroll
    for (int c = 0; c < 3; c++) {
        const float* xp = x + c * H_IN * W_IN + (2 * i) * W_IN + 2 * j;
#pragma unroll
        for (int a = 0; a < 4; a++)
#pragma unroll
            for (int b = 0; b < 4; b++)
                p[c][a][b] = xp[a * W_IN + b];
    }

#pragma unroll
    for (int co = 0; co < 10; co++) {
        float a00 = cb1[co], a01 = cb1[co], a10 = cb1[co], a11 = cb1[co];
#pragma unroll
        for (int c = 0; c < 3; c++)
#pragma unroll
            for (int dy = 0; dy < 3; dy++)
#pragma unroll
                for (int dx = 0; dx < 3; dx++) {
                    float w = cw1[((co * 3 + c) * 3 + dy) * 3 + dx];
                    a00 += p[c][dy][dx] * w;
                    a01 += p[c][dy][dx + 1] * w;
                    a10 += p[c][dy + 1][dx] * w;
                    a11 += p[c][dy + 1][dx + 1] * w;
                }
        float al = cp1[co];
        a00 = (a00 >= 0.f) ? a00 : al * a00;
        a01 = (a01 >= 0.f) ? a01 : al * a01;
        a10 = (a10 >= 0.f) ? a10 : al * a10;
        a11 = (a11 >= 0.f) ? a11 : al * a11;
        float m = fmaxf(fmaxf(a00, a01), fmaxf(a10, a11));
        g_pool1[co * P1 * P1 + i * P1 + j] = m;
    }
}

// ============ K2: conv2(10->16,3x3) + PReLU ============
__global__ void k2() {
    __shared__ float s[10][18][18];
    int tx = threadIdx.x, ty = threadIdx.y;
    int tid = ty * 16 + tx;
    int ox0 = blockIdx.x * 16, oy0 = blockIdx.y * 16;

    for (int t = tid; t < 10 * 18 * 18; t += 256) {
        int c = t / 324;
        int rr = (t % 324) / 18;
        int cc = t % 18;
        int gy = oy0 + rr, gx = ox0 + cc;
        s[c][rr][cc] = (gy < P1 && gx < P1) ? g_pool1[c * P1 * P1 + gy * P1 + gx] : 0.f;
    }
    __syncthreads();

    int ox = ox0 + tx, oy = oy0 + ty;
    if (ox >= C2 || oy >= C2) return;

    float acc[16];
#pragma unroll
    for (int o = 0; o < 16; o++) acc[o] = cb2[o];

#pragma unroll
    for (int c = 0; c < 10; c++) {
        float r[9];
#pragma unroll
        for (int dy = 0; dy < 3; dy++)
#pragma unroll
            for (int dx = 0; dx < 3; dx++)
                r[dy * 3 + dx] = s[c][ty + dy][tx + dx];
#pragma unroll
        for (int o = 0; o < 16; o++)
#pragma unroll
            for (int t9 = 0; t9 < 9; t9++)
                acc[o] += r[t9] * cw2[(o * 10 + c) * 9 + t9];
    }
    int base = oy * C2 + ox;
#pragma unroll
    for (int o = 0; o < 16; o++) {
        float v = acc[o];
        v = (v >= 0.f) ? v : cp2[o] * v;
        g_h2[o * C2 * C2 + base] = v;
    }
}

// ============ K3: conv3(16->32,3x3) + PReLU + cls/reg heads + softmax + hist ============
__global__ void k3() {
    __shared__ float s[16][18][18];
    int tx = threadIdx.x, ty = threadIdx.y;
    int tid = ty * 16 + tx;
    int ox0 = blockIdx.x * 16, oy0 = blockIdx.y * 16;

    for (int t = tid; t < 16 * 18 * 18; t += 256) {
        int c = t / 324;
        int rr = (t % 324) / 18;
        int cc = t % 18;
        int gy = oy0 + rr, gx = ox0 + cc;
        s[c][rr][cc] = (gy < C2 && gx < C2) ? g_h2[c * C2 * C2 + gy * C2 + gx] : 0.f;
    }
    __syncthreads();

    int ox = ox0 + tx, oy = oy0 + ty;
    if (ox >= C3 || oy >= C3) return;

    float acc[32];
#pragma unroll
    for (int o = 0; o < 32; o++) acc[o] = cb3[o];

#pragma unroll
    for (int c = 0; c < 16; c++) {
        float r[9];
#pragma unroll
        for (int dy = 0; dy < 3; dy++)
#pragma unroll
            for (int dx = 0; dx < 3; dx++)
                r[dy * 3 + dx] = s[c][ty + dy][tx + dx];
#pragma unroll
        for (int o = 0; o < 32; o++)
#pragma unroll
            for (int t9 = 0; t9 < 9; t9++)
                acc[o] += r[t9] * cw3[(o * 16 + c) * 9 + t9];
    }
#pragma unroll
    for (int o = 0; o < 32; o++) {
        float v = acc[o];
        acc[o] = (v >= 0.f) ? v : cp3[o] * v;
    }

    float c0 = cba[0], c1 = cba[1];
    float r0 = cbb[0], r1 = cbb[1], r2 = cbb[2], r3 = cbb[3];
#pragma unroll
    for (int o = 0; o < 32; o++) {
        float h = acc[o];
        c0 += h * cwa[o];
        c1 += h * cwa[32 + o];
        r0 += h * cwb[o];
        r1 += h * cwb[32 + o];
        r2 += h * cwb[64 + o];
        r3 += h * cwb[96 + o];
    }
    float mx = fmaxf(c0, c1);
    float e0 = expf(c0 - mx), e1 = expf(c1 - mx);
    float pr = e1 / (e0 + e1);

    int pix = oy * C3 + ox;
    g_prob[pix] = pr;
    g_reg[pix] = make_float4(r0, r1, r2, r3);

    if (pr >= 0.6f) {
        int bin = (int)((pr - 0.6f) * 20480.f);
        if (bin > NBINS - 1) bin = NBINS - 1;
        atomicAdd(&g_hist[bin], 1);
    }
}

// ============ KH: find histogram cutoff bin (1 block, 256 threads) ============
__global__ void kh() {
    __shared__ int csum[256];
    __shared__ int suf[256];
    int t = threadIdx.x;
    int sum = 0;
    for (int b = t * 32; b < t * 32 + 32; b++) sum += g_hist[b];
    csum[t] = sum;
    __syncthreads();
    if (t == 0) {
        int run = 0;
        for (int u = 255; u >= 0; u--) { suf[u] = run; run += csum[u]; }
        if (run < KTOP) g_cut = 0;   // fewer than K candidates -> take all
    }
    __syncthreads();
    if (suf[t] < KTOP && suf[t] + csum[t] >= KTOP) {
        int s = suf[t];
        int B = t * 32;
        for (int b = t * 32 + 31; b >= t * 32; b--) {
            s += g_hist[b];
            if (s >= KTOP) { B = b; break; }
        }
        g_cut = B;
    }
}

// ============ KC: compact candidates >= cutoff bin ============
__global__ void kc() {
    int i = blockIdx.x * 256 + threadIdx.x;
    if (i >= NPIX) return;
    float pr = g_prob[i];
    if (pr < 0.6f) return;
    int bin = (int)((pr - 0.6f) * 20480.f);
    if (bin > NBINS - 1) bin = NBINS - 1;
    if (bin < g_cut) return;
    int pos = atomicAdd(&g_cnt, 1);
    if (pos < CANDMAX) {
        unsigned long long key =
            ((unsigned long long)__float_as_uint(pr) << 32) |
            (unsigned long long)(~(unsigned)i);
        g_cand[pos] = key;
    }
}

// ============ KS: bitonic sort 4096 keys desc, decode boxes (1 block, 1024 thr) ============
__global__ void ks() {
    __shared__ unsigned long long a[CANDMAX];
    int tid = threadIdx.x;
    int cnt = g_cnt;
    if (cnt > CANDMAX) cnt = CANDMAX;
    for (int i = tid; i < CANDMAX; i += 1024) a[i] = (i < cnt) ? g_cand[i] : 0ULL;
    __syncthreads();

    for (int k = 2; k <= CANDMAX; k <<= 1) {
        for (int j = k >> 1; j > 0; j >>= 1) {
            for (int i = tid; i < CANDMAX; i += 1024) {
                int ixj = i ^ j;
                if (ixj > i) {
                    unsigned long long A = a[i], B = a[ixj];
                    bool desc = ((i & k) == 0);
                    if (desc ? (A < B) : (A > B)) { a[i] = B; a[ixj] = A; }
                }
            }
            __syncthreads();
        }
    }

    if (tid < KTOP) {
        unsigned long long key = a[tid];
        unsigned sb = (unsigned)(key >> 32);
        float sc = sb ? __uint_as_float(sb) : -1.0f;
        float x1 = 0.f, y1 = 0.f, x2 = 0.f, y2 = 0.f;
        if (sc >= 0.6f) {
            unsigned idx = ~(unsigned)(key & 0xFFFFFFFFu);
            float4 rg = g_reg[idx];
            float yy = (float)(idx / C3);
            float xx = (float)(idx % C3);
            float cx = (xx * 2.0f + 6.0f) / 0.6f;
            float cy = (yy * 2.0f + 6.0f) / 0.6f;
            const float ww = 12.0f / 0.6f;     // == 20.0f, matches f32(12/0.6)
            x1 = cx - ww * 0.5f + rg.x * ww;
            y1 = cy - ww * 0.5f + rg.y * ww;
            x2 = cx + ww * 0.5f + rg.z * ww;
            y2 = cy + ww * 0.5f + rg.w * ww;
        }
        g_box5[tid * 5 + 0] = x1;
        g_box5[tid * 5 + 1] = y1;
        g_box5[tid * 5 + 2] = x2;
        g_box5[tid * 5 + 3] = y2;
        g_box5[tid * 5 + 4] = sc;
    }
}

// ============ KN: two sequential NMS passes + output (1 block, 512 threads) ============
__global__ void knms(float* __restrict__ out) {
    __shared__ float sx1[KTOP], sy1[KTOP], sx2[KTOP], sy2[KTOP], sar[KTOP];
    __shared__ int skeep[KTOP];
    int t = threadIdx.x;
    float x1 = g_box5[t * 5 + 0];
    float y1 = g_box5[t * 5 + 1];
    float x2 = g_box5[t * 5 + 2];
    float y2 = g_box5[t * 5 + 3];
    float sc = g_box5[t * 5 + 4];
    sx1[t] = x1; sy1[t] = y1; sx2[t] = x2; sy2[t] = y2;
    sar[t] = (x2 - x1) * (y2 - y1);
    skeep[t] = (sc >= 0.6f) ? 1 : 0;
    __syncthreads();

    for (int pass = 0; pass < 2; pass++) {
        float thr = pass ? 0.7f : 0.5f;
        for (int i = 0; i < KTOP; i++) {
            __syncthreads();
            if (skeep[i] && t > i && skeep[t]) {
                float xi1 = fmaxf(sx1[i], sx1[t]);
                float yi1 = fmaxf(sy1[i], sy1[t]);
                float xi2 = fminf(sx2[i], sx2[t]);
                float yi2 = fminf(sy2[i], sy2[t]);
                float inter = fmaxf(xi2 - xi1, 0.f) * fmaxf(yi2 - yi1, 0.f);
                float iou = inter / (sar[i] + sar[t] - inter + 1e-9f);
                if (iou > thr) skeep[t] = 0;
            }
        }
        __syncthreads();
    }

    float m = skeep[t] ? 1.f : 0.f;
    out[t * 5 + 0] = x1 * m;
    out[t * 5 + 1] = y1 * m;
    out[t * 5 + 2] = x2 * m;
    out[t * 5 + 3] = y2 * m;
    out[t * 5 + 4] = sc * m;
}

// ---------------- host launcher ----------------
extern "C" void kernel_launch(void* const* d_in, const int* in_sizes, int n_in,
                              void* d_out, int out_size) {
    const float* x = (const float*)d_in[0];

    cudaMemcpyToSymbolAsync(cw1, d_in[1], 270 * 4, 0, cudaMemcpyDeviceToDevice);
    cudaMemcpyToSymbolAsync(cb1, d_in[2], 10 * 4, 0, cudaMemcpyDeviceToDevice);
    cudaMemcpyToSymbolAsync(cp1, d_in[3], 10 * 4, 0, cudaMemcpyDeviceToDevice);
    cudaMemcpyToSymbolAsync(cw2, d_in[4], 1440 * 4, 0, cudaMemcpyDeviceToDevice);
    cudaMemcpyToSymbolAsync(cb2, d_in[5], 16 * 4, 0, cudaMemcpyDeviceToDevice);
    cudaMemcpyToSymbolAsync(cp2, d_in[6], 16 * 4, 0, cudaMemcpyDeviceToDevice);
    cudaMemcpyToSymbolAsync(cw3, d_in[7], 4608 * 4, 0, cudaMemcpyDeviceToDevice);
    cudaMemcpyToSymbolAsync(cb3, d_in[8], 32 * 4, 0, cudaMemcpyDeviceToDevice);
    cudaMemcpyToSymbolAsync(cp3, d_in[9], 32 * 4, 0, cudaMemcpyDeviceToDevice);
    cudaMemcpyToSymbolAsync(cwa, d_in[10], 64 * 4, 0, cudaMemcpyDeviceToDevice);
    cudaMemcpyToSymbolAsync(cba, d_in[11], 2 * 4, 0, cudaMemcpyDeviceToDevice);
    cudaMemcpyToSymbolAsync(cwb, d_in[12], 128 * 4, 0, cudaMemcpyDeviceToDevice);
    cudaMemcpyToSymbolAsync(cbb, d_in[13], 4 * 4, 0, cudaMemcpyDeviceToDevice);

    void* hp = 0; cudaGetSymbolAddress(&hp, g_hist);
    cudaMemsetAsync(hp, 0, NBINS * sizeof(int));
    void* cp = 0; cudaGetSymbolAddress(&cp, g_cnt);
    cudaMemsetAsync(cp, 0, sizeof(int));

    dim3 b16(16, 16);
    k1<<<dim3(64, 64), b16>>>(x);
    k2<<<dim3(64, 64), b16>>>();
    k3<<<dim3(64, 64), b16>>>();
    kh<<<1, 256>>>();
    kc<<<(NPIX + 255) / 256, 256>>>();
    ks<<<1, 1024>>>();
    knms<<<1, 512>>>((float*)d_out);
}